// round 15
// baseline (speedup 1.0000x reference)
#include <cuda_runtime.h>
#include <cstdint>

#define cB  2
#define cN  2065
#define cNP 2048
#define cNT 16
#define cE  512
#define cH  8
#define cE3 1536
#define NBH (cB*cH)
#define SCALE_QK 0.125f
#define EPS_BAL  1e-6f
#define PROWS 2176
#define PSTR  72
#define NCH   33
#define OHSZ  ((size_t)cB * cN * cE)

__device__ float g_qkv [(size_t)cB * cN * cE3];
__device__ float g_oh  [OHSZ];
__device__ float g_ohp [2 * OHSZ];
__device__ float g_fac [(size_t)NBH * cN * 4];
__device__ float g_part[(size_t)NBH * PROWS * PSTR];

__device__ __forceinline__ uint32_t f2tf32(float x) {
    uint32_t r; asm("cvt.rna.tf32.f32 %0, %1;" : "=r"(r) : "f"(x)); return r;
}
__device__ __forceinline__ void mma_tf32(float* c, uint32_t a0, uint32_t a1,
                                         uint32_t a2, uint32_t a3,
                                         uint32_t b0, uint32_t b1) {
    asm volatile(
        "mma.sync.aligned.m16n8k8.row.col.f32.tf32.tf32.f32 "
        "{%0,%1,%2,%3}, {%4,%5,%6,%7}, {%8,%9}, {%0,%1,%2,%3};"
        : "+f"(c[0]), "+f"(c[1]), "+f"(c[2]), "+f"(c[3])
        : "r"(a0), "r"(a1), "r"(a2), "r"(a3), "r"(b0), "r"(b1));
}
__device__ __forceinline__ void cp_async4(uint32_t dst, const void* src, bool ok) {
    int sz = ok ? 4 : 0;
    asm volatile("cp.async.ca.shared.global [%0], [%1], 4, %2;"
                 :: "r"(dst), "l"(src), "r"(sz));
}
__device__ __forceinline__ void cp_commit() {
    asm volatile("cp.async.commit_group;" ::: "memory");
}
__device__ __forceinline__ void cp_wait1() {
    asm volatile("cp.async.wait_group 1;" ::: "memory");
}

extern __shared__ float dynsm[];

// --------------------- tf32 GEMM + bias (projections): C = A@W + bias
__global__ __launch_bounds__(256)
void gemm_tf32_bias(const float* __restrict__ A, const float* __restrict__ W,
                    const float* __restrict__ bias, float* __restrict__ C,
                    int M, int Nc, int K) {
    __shared__ uint32_t As[128 * 36];   // [m][k]
    __shared__ uint32_t Ws[128 * 36];   // [n][k] (W transposed)
    const int t = threadIdx.x, lane = t & 31, wid = t >> 5;
    const int wrow = wid >> 2, wcol = wid & 3;
    const int m0 = blockIdx.y * 128, n0 = blockIdx.x * 128;
    const int arow = t >> 3, acol = (t & 7) * 4;
    const int wrk  = t >> 5, wcn  = (t & 31) * 4;

    float4 ra[4], rw[4];
    const int nchunks = K >> 5;

    #pragma unroll
    for (int i = 0; i < 4; i++) {
        int r = arow + i * 32;
        ra[i] = (m0 + r < M) ? *(const float4*)&A[(size_t)(m0 + r) * K + acol]
                             : make_float4(0.f, 0.f, 0.f, 0.f);
        rw[i] = *(const float4*)&W[(size_t)(wrk + i * 8) * Nc + n0 + wcn];
    }

    float acc[4][4][4] = {};

    for (int c = 0; c < nchunks; c++) {
        __syncthreads();
        #pragma unroll
        for (int i = 0; i < 4; i++) {
            int r = arow + i * 32;
            *(uint4*)&As[r * 36 + acol] =
                make_uint4(f2tf32(ra[i].x), f2tf32(ra[i].y), f2tf32(ra[i].z), f2tf32(ra[i].w));
            int k = wrk + i * 8;
            Ws[(wcn + 0) * 36 + k] = f2tf32(rw[i].x);
            Ws[(wcn + 1) * 36 + k] = f2tf32(rw[i].y);
            Ws[(wcn + 2) * 36 + k] = f2tf32(rw[i].z);
            Ws[(wcn + 3) * 36 + k] = f2tf32(rw[i].w);
        }
        __syncthreads();

        if (c + 1 < nchunks) {
            const int k0c = (c + 1) * 32;
            #pragma unroll
            for (int i = 0; i < 4; i++) {
                int r = arow + i * 32;
                ra[i] = (m0 + r < M) ? *(const float4*)&A[(size_t)(m0 + r) * K + k0c + acol]
                                     : make_float4(0.f, 0.f, 0.f, 0.f);
                rw[i] = *(const float4*)&W[(size_t)(k0c + wrk + i * 8) * Nc + n0 + wcn];
            }
        }

        #pragma unroll
        for (int kk = 0; kk < 4; kk++) {
            const int k0 = kk * 8;
            uint32_t a[4][4], bq[4][2];
            #pragma unroll
            for (int mt = 0; mt < 4; mt++) {
                int r = wrow*64 + mt*16 + (lane >> 2);
                a[mt][0] = As[r*36     + k0     + (lane & 3)];
                a[mt][1] = As[(r+8)*36 + k0     + (lane & 3)];
                a[mt][2] = As[r*36     + k0 + 4 + (lane & 3)];
                a[mt][3] = As[(r+8)*36 + k0 + 4 + (lane & 3)];
            }
            #pragma unroll
            for (int nt = 0; nt < 4; nt++) {
                int cc = wcol*32 + nt*8 + (lane >> 2);
                bq[nt][0] = Ws[cc*36 + k0     + (lane & 3)];
                bq[nt][1] = Ws[cc*36 + k0 + 4 + (lane & 3)];
            }
            #pragma unroll
            for (int mt = 0; mt < 4; mt++)
                #pragma unroll
                for (int nt = 0; nt < 4; nt++)
                    mma_tf32(acc[mt][nt], a[mt][0], a[mt][1], a[mt][2], a[mt][3],
                             bq[nt][0], bq[nt][1]);
        }
    }

    #pragma unroll
    for (int mt = 0; mt < 4; mt++) {
        #pragma unroll
        for (int nt = 0; nt < 4; nt++) {
            int gr = m0 + wrow*64 + mt*16 + (lane >> 2);
            int gc = n0 + wcol*32 + nt*8 + (lane & 3) * 2;
            float b0 = bias[gc], b1 = bias[gc + 1];
            if (gr < M)
                *(float2*)&C[(size_t)gr * Nc + gc] =
                    make_float2(acc[mt][nt][0] + b0, acc[mt][nt][1] + b1);
            if (gr + 8 < M)
                *(float2*)&C[(size_t)(gr + 8) * Nc + gc] =
                    make_float2(acc[mt][nt][2] + b0, acc[mt][nt][3] + b1);
        }
    }
}

// ------------------------------- tf32 mma.sync QK^T + fused segment partials
__global__ __launch_bounds__(256)
void qk_kernel(const float* __restrict__ qkv, float* __restrict__ A_raw,
               float* __restrict__ part) {
    const int t = threadIdx.x, lane = t & 31, wid = t >> 5;
    const int wrow = wid >> 2, wcol = wid & 3;
    const int bh = blockIdx.z, b = bh >> 3, h = bh & 7;
    const int n0 = blockIdx.y * 128;
    const int mtile = blockIdx.x, m0 = mtile * 128;

    uint32_t* qs = (uint32_t*)dynsm;       // [128][68]
    uint32_t* ks = qs + 128 * 68;
    float* res = dynsm;                    // output bounce alias [128][132]

    const float* qb = qkv + (size_t)b * cN * cE3 + h * 64;
    const float* kb = qb + cE;

    #pragma unroll
    for (int i = 0; i < 8; i++) {
        int idx = t + i * 256;
        int row = idx >> 4, q4 = idx & 15;
        float4 qv = make_float4(0.f,0.f,0.f,0.f), kv = qv;
        if (n0 + row < cN) qv = *(const float4*)&qb[(size_t)(n0+row)*cE3 + q4*4];
        if (m0 + row < cN) kv = *(const float4*)&kb[(size_t)(m0+row)*cE3 + q4*4];
        *(uint4*)&qs[row*68 + q4*4] =
            make_uint4(f2tf32(qv.x), f2tf32(qv.y), f2tf32(qv.z), f2tf32(qv.w));
        *(uint4*)&ks[row*68 + q4*4] =
            make_uint4(f2tf32(kv.x), f2tf32(kv.y), f2tf32(kv.z), f2tf32(kv.w));
    }
    __syncthreads();

    float acc[4][4][4] = {};
    #pragma unroll
    for (int kk = 0; kk < 8; kk++) {
        const int k0 = kk * 8;
        uint32_t a[4][4], bq[4][2];
        #pragma unroll
        for (int mt = 0; mt < 4; mt++) {
            int r = wrow*64 + mt*16 + (lane >> 2);
            a[mt][0] = qs[r*68     + k0     + (lane & 3)];
            a[mt][1] = qs[(r+8)*68 + k0     + (lane & 3)];
            a[mt][2] = qs[r*68     + k0 + 4 + (lane & 3)];
            a[mt][3] = qs[(r+8)*68 + k0 + 4 + (lane & 3)];
        }
        #pragma unroll
        for (int nt = 0; nt < 4; nt++) {
            int cc = wcol*32 + nt*8 + (lane >> 2);
            bq[nt][0] = ks[cc*68 + k0     + (lane & 3)];
            bq[nt][1] = ks[cc*68 + k0 + 4 + (lane & 3)];
        }
        #pragma unroll
        for (int mt = 0; mt < 4; mt++)
            #pragma unroll
            for (int nt = 0; nt < 4; nt++)
                mma_tf32(acc[mt][nt], a[mt][0], a[mt][1], a[mt][2], a[mt][3],
                         bq[nt][0], bq[nt][1]);
    }
    __syncthreads();

    #pragma unroll
    for (int mt = 0; mt < 4; mt++) {
        int r = wrow*64 + mt*16 + (lane >> 2);
        #pragma unroll
        for (int nt = 0; nt < 4; nt++) {
            int cc = wcol*32 + nt*8 + (lane & 3)*2;
            *(float2*)&res[r*132 + cc]     = make_float2(acc[mt][nt][0], acc[mt][nt][1]);
            *(float2*)&res[(r+8)*132 + cc] = make_float2(acc[mt][nt][2], acc[mt][nt][3]);
        }
    }
    __syncthreads();

    {
        int row = t >> 1, cbase = (t & 1) * 64;
        float sp = 0.f, sep = 0.f, st = 0.f, set = 0.f, vc = 0.f;
        if (n0 + row < cN) {
            if (mtile < 16) {
                #pragma unroll 4
                for (int j = 0; j < 64; j++) {
                    float v = res[row*132 + cbase + j] * SCALE_QK;
                    sp += v; sep += __expf(v);
                }
            } else if (cbase == 0) {
                for (int j = 0; j < 16; j++) {
                    float v = res[row*132 + j] * SCALE_QK;
                    st += v; set += __expf(v);
                }
                vc = res[row*132 + 16] * SCALE_QK;
            }
        }
        sp  += __shfl_xor_sync(0xffffffffu, sp,  1);
        sep += __shfl_xor_sync(0xffffffffu, sep, 1);
        st  += __shfl_xor_sync(0xffffffffu, st,  1);
        set += __shfl_xor_sync(0xffffffffu, set, 1);
        vc  += __shfl_xor_sync(0xffffffffu, vc,  1);
        if (!(t & 1) && (n0 + row) < cN) {
            float* pp = &part[((size_t)bh * PROWS + n0 + row) * PSTR + mtile * 4];
            pp[0] = sp; pp[1] = sep; pp[2] = st; pp[3] = set;
            if (mtile == 16)
                part[((size_t)bh * PROWS + n0 + row) * PSTR + 68] = vc;
        }
    }

    const size_t arbase = (size_t)bh * cN * cN;
    for (int i = 0; i < 64; i++) {
        int idx = t + i * 256;
        int r = idx >> 7, c = idx & 127;
        int gr = n0 + r, gc = m0 + c;
        if (gr < cN && gc < cN)
            A_raw[arbase + (size_t)gr * cN + gc] = res[r*132 + c] * SCALE_QK;
    }
}

// ------------------------------------------------------------ finalize fac
__global__ void finalize_kernel(const float* __restrict__ part, float* __restrict__ fac) {
    int idx = blockIdx.x * 256 + threadIdx.x;
    if (idx >= NBH * cN) return;
    int bh = idx / cN, n = idx - bh * cN;
    const float* p = part + ((size_t)bh * PROWS + n) * PSTR;
    float SP = 0.f, SEP = 0.f, ST = 0.f, SET = 0.f;
    #pragma unroll
    for (int mt = 0; mt < 17; mt++) {
        SP += p[mt*4]; SEP += p[mt*4+1]; ST += p[mt*4+2]; SET += p[mt*4+3];
    }
    float vc = p[68];
    float ep = __expf(SP * (1.f / (float)cNP));
    float et = __expf(ST * (1.f / (float)cNT));
    float ec = __expf(vc);
    float s = ep + et + ec;
    float* fp = &fac[(size_t)idx * 4];
    fp[0] = (ep / s) / (SEP + EPS_BAL);
    fp[1] = (et / s) / (SET + EPS_BAL);
    fp[2] = (ec / s) / (ec  + EPS_BAL);
    fp[3] = 0.f;
}

// --------------------------------------- streaming A materialization
__global__ __launch_bounds__(256)
void mat_kernel(const float* __restrict__ A_raw, const float* __restrict__ fac,
                float* __restrict__ A) {
    const size_t row = blockIdx.x;
    const float* src = A_raw + row * cN;
    float* dst = A + row * cN;
    const float4 f = *(const float4*)&fac[row * 4];
    const int t = threadIdx.x;
    #pragma unroll
    for (int i = 0; i < 8; i++) {
        int idx = t + i * 256;
        dst[idx] = __expf(src[idx]) * f.x;
    }
    if (t < 17) {
        int idx = cNP + t;
        float ff = (t < 16) ? f.y : f.z;
        dst[idx] = __expf(src[idx]) * ff;
    }
}

// --------------------- tf32 AV GEMM, split-K=2, cp.async double-buffered.
// Grid (17, NBH, 2). Slice z covers chunks [z*17, z*17+nch). Partial OH
// written to ohp slice z; reduce_oh sums slices (fixed order, deterministic).
__global__ __launch_bounds__(256)
void avg_kernel(const float* __restrict__ A, const float* __restrict__ qkv,
                float* __restrict__ ohp) {
    const int t = threadIdx.x, lane = t & 31, wid = t >> 5;
    const int wrow = wid >> 1, wcol = wid & 1;
    const int bh = blockIdx.y, b = bh >> 3, h = bh & 7;
    const int n0 = blockIdx.x * 128;
    const int z = blockIdx.z;
    const int c0 = z * 17;
    const int nch = z ? 16 : 17;

    float*    Ab = dynsm;                              // [2][128][68] fp32
    uint32_t* Vb = (uint32_t*)(dynsm + 2 * 128 * 68);  // [2][64][68] tf32 V^T
    const uint32_t sAb = (uint32_t)__cvta_generic_to_shared(Ab);

    const float* Arow = A + (size_t)bh * cN * cN;
    const float* vb = qkv + (size_t)b * cN * cE3 + 2 * cE + h * 64;

    const int vd = t & 63, vmg = t >> 6;
    float acc[2][4][4] = {};

    {
        const int m0 = c0 * 64;
        #pragma unroll
        for (int i = 0; i < 32; i++) {
            int idx = t + i * 256;
            int row = idx >> 6, col = idx & 63;
            int n = n0 + row, m = m0 + col;
            bool ok = (n < cN) && (m < cN);
            const float* src = &Arow[(size_t)(ok ? n : 0) * cN + (ok ? m : 0)];
            cp_async4(sAb + (uint32_t)((row*68 + col) * 4), src, ok);
        }
        uint32_t* Vd = Vb + vd * 68;
        #pragma unroll
        for (int j = 0; j < 4; j++) {
            int ml = vmg * 16 + j * 4;
            float4 v;
            v.x = (m0+ml+0 < cN) ? vb[(size_t)(m0+ml+0)*cE3 + vd] : 0.f;
            v.y = (m0+ml+1 < cN) ? vb[(size_t)(m0+ml+1)*cE3 + vd] : 0.f;
            v.z = (m0+ml+2 < cN) ? vb[(size_t)(m0+ml+2)*cE3 + vd] : 0.f;
            v.w = (m0+ml+3 < cN) ? vb[(size_t)(m0+ml+3)*cE3 + vd] : 0.f;
            *(uint4*)&Vd[ml] = make_uint4(f2tf32(v.x), f2tf32(v.y),
                                          f2tf32(v.z), f2tf32(v.w));
        }
    }
    cp_commit();

    for (int cc = 0; cc < nch; cc++) {
        const int c = c0 + cc;
        if (cc + 1 < nch) {
            const int m0 = (c + 1) * 64;
            const uint32_t bufo = (uint32_t)(((cc + 1) & 1) * 128 * 68 * 4);
            #pragma unroll
            for (int i = 0; i < 32; i++) {
                int idx = t + i * 256;
                int row = idx >> 6, col = idx & 63;
                int n = n0 + row, m = m0 + col;
                bool ok = (n < cN) && (m < cN);
                const float* src = &Arow[(size_t)(ok ? n : 0) * cN + (ok ? m : 0)];
                cp_async4(sAb + bufo + (uint32_t)((row*68 + col) * 4), src, ok);
            }
            uint32_t* Vd = Vb + ((cc + 1) & 1) * 64 * 68 + vd * 68;
            #pragma unroll
            for (int j = 0; j < 4; j++) {
                int ml = vmg * 16 + j * 4;
                float4 v;
                v.x = (m0+ml+0 < cN) ? vb[(size_t)(m0+ml+0)*cE3 + vd] : 0.f;
                v.y = (m0+ml+1 < cN) ? vb[(size_t)(m0+ml+1)*cE3 + vd] : 0.f;
                v.z = (m0+ml+2 < cN) ? vb[(size_t)(m0+ml+2)*cE3 + vd] : 0.f;
                v.w = (m0+ml+3 < cN) ? vb[(size_t)(m0+ml+3)*cE3 + vd] : 0.f;
                *(uint4*)&Vd[ml] = make_uint4(f2tf32(v.x), f2tf32(v.y),
                                              f2tf32(v.z), f2tf32(v.w));
            }
        }
        cp_commit();
        cp_wait1();
        __syncthreads();

        const float*    Ac = Ab + (cc & 1) * 128 * 68;
        const uint32_t* Vc = Vb + (cc & 1) * 64 * 68;
        #pragma unroll
        for (int kk = 0; kk < 8; kk++) {
            const int k0 = kk * 8;
            uint32_t a[2][4], bq[4][2];
            #pragma unroll
            for (int mt = 0; mt < 2; mt++) {
                int r = wrow*32 + mt*16 + (lane >> 2);
                a[mt][0] = f2tf32(Ac[r*68     + k0     + (lane & 3)]);
                a[mt][1] = f2tf32(Ac[(r+8)*68 + k0     + (lane & 3)]);
                a[mt][2] = f2tf32(Ac[r*68     + k0 + 4 + (lane & 3)]);
                a[mt][3] = f2tf32(Ac[(r+8)*68 + k0 + 4 + (lane & 3)]);
            }
            #pragma unroll
            for (int nt = 0; nt < 4; nt++) {
                int dd = wcol*32 + nt*8 + (lane >> 2);
                bq[nt][0] = Vc[dd*68 + k0     + (lane & 3)];
                bq[nt][1] = Vc[dd*68 + k0 + 4 + (lane & 3)];
            }
            #pragma unroll
            for (int mt = 0; mt < 2; mt++)
                #pragma unroll
                for (int nt = 0; nt < 4; nt++)
                    mma_tf32(acc[mt][nt], a[mt][0], a[mt][1], a[mt][2], a[mt][3],
                             bq[nt][0], bq[nt][1]);
        }
        __syncthreads();
    }

    float* dstb = ohp + (size_t)z * OHSZ + (size_t)b * cN * cE + h * 64;
    #pragma unroll
    for (int mt = 0; mt < 2; mt++) {
        #pragma unroll
        for (int nt = 0; nt < 4; nt++) {
            int n = n0 + wrow*32 + mt*16 + (lane >> 2);
            int d = wcol*32 + nt*8 + (lane & 3)*2;
            if (n < cN)
                *(float2*)&dstb[(size_t)n * cE + d] =
                    make_float2(acc[mt][nt][0], acc[mt][nt][1]);
            if (n + 8 < cN)
                *(float2*)&dstb[(size_t)(n + 8) * cE + d] =
                    make_float2(acc[mt][nt][2], acc[mt][nt][3]);
        }
    }
}

// ------------------------------------------ reduce split-K partials: OH=p0+p1
__global__ __launch_bounds__(256)
void reduce_oh(const float* __restrict__ ohp, float* __restrict__ OH) {
    size_t i = ((size_t)blockIdx.x * 256 + threadIdx.x) * 4;
    if (i >= OHSZ) return;
    float4 a = *(const float4*)&ohp[i];
    float4 b = *(const float4*)&ohp[OHSZ + i];
    float4 r;
    r.x = a.x + b.x; r.y = a.y + b.y; r.z = a.z + b.z; r.w = a.w + b.w;
    *(float4*)&OH[i] = r;
}

// ---------------------------------------------------------------------------
extern "C" void kernel_launch(void* const* d_in, const int* in_sizes, int n_in,
                              void* d_out, int out_size) {
    const float* x     = (const float*)d_in[0];
    const float* w_qkv = (const float*)d_in[1];
    const float* b_qkv = (const float*)d_in[2];
    const float* w_out = (const float*)d_in[3];
    const float* b_out = (const float*)d_in[4];

    float* out   = (float*)d_out;
    float* A     = out + (size_t)cB * cN * cE;
    float* A_raw = A   + (size_t)NBH * cN * cN;

    float *qkv = nullptr, *oh = nullptr, *ohp = nullptr, *facp = nullptr, *partp = nullptr;
    cudaGetSymbolAddress((void**)&qkv,   g_qkv);
    cudaGetSymbolAddress((void**)&oh,    g_oh);
    cudaGetSymbolAddress((void**)&ohp,   g_ohp);
    cudaGetSymbolAddress((void**)&facp,  g_fac);
    cudaGetSymbolAddress((void**)&partp, g_part);

    const int M = cB * cN;
    const int QK_SMEM  = 2 * 128 * 68 * 4;                 // 69632 B
    const int AVG_SMEM = (2*128*68 + 2*64*68) * 4;         // 104448 B
    cudaFuncSetAttribute(qk_kernel,  cudaFuncAttributeMaxDynamicSharedMemorySize, QK_SMEM);
    cudaFuncSetAttribute(avg_kernel, cudaFuncAttributeMaxDynamicSharedMemorySize, AVG_SMEM);

    gemm_tf32_bias<<<dim3(cE3/128, (M+127)/128), 256>>>(x, w_qkv, b_qkv, qkv, M, cE3, cE);
    qk_kernel<<<dim3(17, 17, NBH), 256, QK_SMEM>>>(qkv, A_raw, partp);
    finalize_kernel<<<(NBH*cN + 255)/256, 256>>>(partp, facp);
    mat_kernel<<<NBH * cN, 256>>>(A_raw, facp, A);
    avg_kernel<<<dim3(17, NBH, 2), 256, AVG_SMEM>>>(A, qkv, ohp);
    reduce_oh<<<(int)((OHSZ/4 + 255)/256), 256>>>(ohp, oh);
    gemm_tf32_bias<<<dim3(cE/128, (M+127)/128), 256>>>(oh, w_out, b_out, out, M, cE, cE);
}

// round 16
// speedup vs baseline: 1.0260x; 1.0260x over previous
#include <cuda_runtime.h>
#include <cstdint>

#define cB  2
#define cN  2065
#define cNP 2048
#define cNT 16
#define cE  512
#define cH  8
#define cE3 1536
#define NBH (cB*cH)
#define SCALE_QK 0.125f
#define EPS_BAL  1e-6f
#define PROWS 2176
#define PSTR  72
#define NCH   33     // ceil(2065/64) k-chunks

__device__ float g_qkv [(size_t)cB * cN * cE3];
__device__ float g_oh  [(size_t)cB * cN * cE];
__device__ float g_fac [(size_t)NBH * cN * 4];
__device__ float g_part[(size_t)NBH * PROWS * PSTR];

__device__ __forceinline__ uint32_t f2tf32(float x) {
    uint32_t r; asm("cvt.rna.tf32.f32 %0, %1;" : "=r"(r) : "f"(x)); return r;
}
__device__ __forceinline__ void mma_tf32(float* c, uint32_t a0, uint32_t a1,
                                         uint32_t a2, uint32_t a3,
                                         uint32_t b0, uint32_t b1) {
    asm volatile(
        "mma.sync.aligned.m16n8k8.row.col.f32.tf32.tf32.f32 "
        "{%0,%1,%2,%3}, {%4,%5,%6,%7}, {%8,%9}, {%0,%1,%2,%3};"
        : "+f"(c[0]), "+f"(c[1]), "+f"(c[2]), "+f"(c[3])
        : "r"(a0), "r"(a1), "r"(a2), "r"(a3), "r"(b0), "r"(b1));
}
__device__ __forceinline__ void cp_async4(uint32_t dst, const void* src, bool ok) {
    int sz = ok ? 4 : 0;
    asm volatile("cp.async.ca.shared.global [%0], [%1], 4, %2;"
                 :: "r"(dst), "l"(src), "r"(sz));
}
__device__ __forceinline__ void cp_commit() {
    asm volatile("cp.async.commit_group;" ::: "memory");
}
__device__ __forceinline__ void cp_wait1() {
    asm volatile("cp.async.wait_group 1;" ::: "memory");
}

extern __shared__ float dynsm[];

// --------------------- tf32 GEMM + bias (projections): C = A@W + bias
__global__ __launch_bounds__(256)
void gemm_tf32_bias(const float* __restrict__ A, const float* __restrict__ W,
                    const float* __restrict__ bias, float* __restrict__ C,
                    int M, int Nc, int K) {
    __shared__ uint32_t As[128 * 36];   // [m][k]
    __shared__ uint32_t Ws[128 * 36];   // [n][k] (W transposed)
    const int t = threadIdx.x, lane = t & 31, wid = t >> 5;
    const int wrow = wid >> 2, wcol = wid & 3;
    const int m0 = blockIdx.y * 128, n0 = blockIdx.x * 128;
    const int arow = t >> 3, acol = (t & 7) * 4;
    const int wrk  = t >> 5, wcn  = (t & 31) * 4;

    float4 ra[4], rw[4];
    const int nchunks = K >> 5;

    #pragma unroll
    for (int i = 0; i < 4; i++) {
        int r = arow + i * 32;
        ra[i] = (m0 + r < M) ? *(const float4*)&A[(size_t)(m0 + r) * K + acol]
                             : make_float4(0.f, 0.f, 0.f, 0.f);
        rw[i] = *(const float4*)&W[(size_t)(wrk + i * 8) * Nc + n0 + wcn];
    }

    float acc[4][4][4] = {};

    for (int c = 0; c < nchunks; c++) {
        __syncthreads();
        #pragma unroll
        for (int i = 0; i < 4; i++) {
            int r = arow + i * 32;
            *(uint4*)&As[r * 36 + acol] =
                make_uint4(f2tf32(ra[i].x), f2tf32(ra[i].y), f2tf32(ra[i].z), f2tf32(ra[i].w));
            int k = wrk + i * 8;
            Ws[(wcn + 0) * 36 + k] = f2tf32(rw[i].x);
            Ws[(wcn + 1) * 36 + k] = f2tf32(rw[i].y);
            Ws[(wcn + 2) * 36 + k] = f2tf32(rw[i].z);
            Ws[(wcn + 3) * 36 + k] = f2tf32(rw[i].w);
        }
        __syncthreads();

        if (c + 1 < nchunks) {
            const int k0c = (c + 1) * 32;
            #pragma unroll
            for (int i = 0; i < 4; i++) {
                int r = arow + i * 32;
                ra[i] = (m0 + r < M) ? *(const float4*)&A[(size_t)(m0 + r) * K + k0c + acol]
                                     : make_float4(0.f, 0.f, 0.f, 0.f);
                rw[i] = *(const float4*)&W[(size_t)(k0c + wrk + i * 8) * Nc + n0 + wcn];
            }
        }

        #pragma unroll
        for (int kk = 0; kk < 4; kk++) {
            const int k0 = kk * 8;
            uint32_t a[4][4], bq[4][2];
            #pragma unroll
            for (int mt = 0; mt < 4; mt++) {
                int r = wrow*64 + mt*16 + (lane >> 2);
                a[mt][0] = As[r*36     + k0     + (lane & 3)];
                a[mt][1] = As[(r+8)*36 + k0     + (lane & 3)];
                a[mt][2] = As[r*36     + k0 + 4 + (lane & 3)];
                a[mt][3] = As[(r+8)*36 + k0 + 4 + (lane & 3)];
            }
            #pragma unroll
            for (int nt = 0; nt < 4; nt++) {
                int cc = wcol*32 + nt*8 + (lane >> 2);
                bq[nt][0] = Ws[cc*36 + k0     + (lane & 3)];
                bq[nt][1] = Ws[cc*36 + k0 + 4 + (lane & 3)];
            }
            #pragma unroll
            for (int mt = 0; mt < 4; mt++)
                #pragma unroll
                for (int nt = 0; nt < 4; nt++)
                    mma_tf32(acc[mt][nt], a[mt][0], a[mt][1], a[mt][2], a[mt][3],
                             bq[nt][0], bq[nt][1]);
        }
    }

    #pragma unroll
    for (int mt = 0; mt < 4; mt++) {
        #pragma unroll
        for (int nt = 0; nt < 4; nt++) {
            int gr = m0 + wrow*64 + mt*16 + (lane >> 2);
            int gc = n0 + wcol*32 + nt*8 + (lane & 3) * 2;
            float b0 = bias[gc], b1 = bias[gc + 1];
            if (gr < M)
                *(float2*)&C[(size_t)gr * Nc + gc] =
                    make_float2(acc[mt][nt][0] + b0, acc[mt][nt][1] + b1);
            if (gr + 8 < M)
                *(float2*)&C[(size_t)(gr + 8) * Nc + gc] =
                    make_float2(acc[mt][nt][2] + b0, acc[mt][nt][3] + b1);
        }
    }
}

// ------------------------------- tf32 mma.sync QK^T + fused segment partials
// (R13 structure; store phase moved BEFORE partial phase so the 273MB A_raw
//  store stream drains while the MUFU expf partial chain executes.)
__global__ __launch_bounds__(256)
void qk_kernel(const float* __restrict__ qkv, float* __restrict__ A_raw,
               float* __restrict__ part) {
    const int t = threadIdx.x, lane = t & 31, wid = t >> 5;
    const int wrow = wid >> 2, wcol = wid & 3;
    const int bh = blockIdx.z, b = bh >> 3, h = bh & 7;
    const int n0 = blockIdx.y * 128;
    const int mtile = blockIdx.x, m0 = mtile * 128;

    uint32_t* qs = (uint32_t*)dynsm;       // [128][68]
    uint32_t* ks = qs + 128 * 68;
    float* res = dynsm;                    // output bounce alias [128][132]

    const float* qb = qkv + (size_t)b * cN * cE3 + h * 64;
    const float* kb = qb + cE;

    #pragma unroll
    for (int i = 0; i < 8; i++) {
        int idx = t + i * 256;
        int row = idx >> 4, q4 = idx & 15;
        float4 qv = make_float4(0.f,0.f,0.f,0.f), kv = qv;
        if (n0 + row < cN) qv = *(const float4*)&qb[(size_t)(n0+row)*cE3 + q4*4];
        if (m0 + row < cN) kv = *(const float4*)&kb[(size_t)(m0+row)*cE3 + q4*4];
        *(uint4*)&qs[row*68 + q4*4] =
            make_uint4(f2tf32(qv.x), f2tf32(qv.y), f2tf32(qv.z), f2tf32(qv.w));
        *(uint4*)&ks[row*68 + q4*4] =
            make_uint4(f2tf32(kv.x), f2tf32(kv.y), f2tf32(kv.z), f2tf32(kv.w));
    }
    __syncthreads();

    float acc[4][4][4] = {};
    #pragma unroll
    for (int kk = 0; kk < 8; kk++) {
        const int k0 = kk * 8;
        uint32_t a[4][4], bq[4][2];
        #pragma unroll
        for (int mt = 0; mt < 4; mt++) {
            int r = wrow*64 + mt*16 + (lane >> 2);
            a[mt][0] = qs[r*68     + k0     + (lane & 3)];
            a[mt][1] = qs[(r+8)*68 + k0     + (lane & 3)];
            a[mt][2] = qs[r*68     + k0 + 4 + (lane & 3)];
            a[mt][3] = qs[(r+8)*68 + k0 + 4 + (lane & 3)];
        }
        #pragma unroll
        for (int nt = 0; nt < 4; nt++) {
            int cc = wcol*32 + nt*8 + (lane >> 2);
            bq[nt][0] = ks[cc*68 + k0     + (lane & 3)];
            bq[nt][1] = ks[cc*68 + k0 + 4 + (lane & 3)];
        }
        #pragma unroll
        for (int mt = 0; mt < 4; mt++)
            #pragma unroll
            for (int nt = 0; nt < 4; nt++)
                mma_tf32(acc[mt][nt], a[mt][0], a[mt][1], a[mt][2], a[mt][3],
                         bq[nt][0], bq[nt][1]);
    }
    __syncthreads();

    #pragma unroll
    for (int mt = 0; mt < 4; mt++) {
        int r = wrow*64 + mt*16 + (lane >> 2);
        #pragma unroll
        for (int nt = 0; nt < 4; nt++) {
            int cc = wcol*32 + nt*8 + (lane & 3)*2;
            *(float2*)&res[r*132 + cc]     = make_float2(acc[mt][nt][0], acc[mt][nt][1]);
            *(float2*)&res[(r+8)*132 + cc] = make_float2(acc[mt][nt][2], acc[mt][nt][3]);
        }
    }
    __syncthreads();

    // ---- A_raw stores FIRST: get the HBM stream draining early ----
    const size_t arbase = (size_t)bh * cN * cN;
    for (int i = 0; i < 64; i++) {
        int idx = t + i * 256;
        int r = idx >> 7, c = idx & 127;
        int gr = n0 + r, gc = m0 + c;
        if (gr < cN && gc < cN)
            A_raw[arbase + (size_t)gr * cN + gc] = res[r*132 + c] * SCALE_QK;
    }

    // ---- segment partials overlap the store drain ----
    {
        int row = t >> 1, cbase = (t & 1) * 64;
        float sp = 0.f, sep = 0.f, st = 0.f, set = 0.f, vc = 0.f;
        if (n0 + row < cN) {
            if (mtile < 16) {
                #pragma unroll 4
                for (int j = 0; j < 64; j++) {
                    float v = res[row*132 + cbase + j] * SCALE_QK;
                    sp += v; sep += __expf(v);
                }
            } else if (cbase == 0) {
                for (int j = 0; j < 16; j++) {
                    float v = res[row*132 + j] * SCALE_QK;
                    st += v; set += __expf(v);
                }
                vc = res[row*132 + 16] * SCALE_QK;
            }
        }
        sp  += __shfl_xor_sync(0xffffffffu, sp,  1);
        sep += __shfl_xor_sync(0xffffffffu, sep, 1);
        st  += __shfl_xor_sync(0xffffffffu, st,  1);
        set += __shfl_xor_sync(0xffffffffu, set, 1);
        vc  += __shfl_xor_sync(0xffffffffu, vc,  1);
        if (!(t & 1) && (n0 + row) < cN) {
            float* pp = &part[((size_t)bh * PROWS + n0 + row) * PSTR + mtile * 4];
            pp[0] = sp; pp[1] = sep; pp[2] = st; pp[3] = set;
            if (mtile == 16)
                part[((size_t)bh * PROWS + n0 + row) * PSTR + 68] = vc;
        }
    }
}

// ------------------------------------------------------------ finalize fac
__global__ void finalize_kernel(const float* __restrict__ part, float* __restrict__ fac) {
    int idx = blockIdx.x * 256 + threadIdx.x;
    if (idx >= NBH * cN) return;
    int bh = idx / cN, n = idx - bh * cN;
    const float* p = part + ((size_t)bh * PROWS + n) * PSTR;
    float SP = 0.f, SEP = 0.f, ST = 0.f, SET = 0.f;
    #pragma unroll
    for (int mt = 0; mt < 17; mt++) {
        SP += p[mt*4]; SEP += p[mt*4+1]; ST += p[mt*4+2]; SET += p[mt*4+3];
    }
    float vc = p[68];
    float ep = __expf(SP * (1.f / (float)cNP));
    float et = __expf(ST * (1.f / (float)cNT));
    float ec = __expf(vc);
    float s = ep + et + ec;
    float* fp = &fac[(size_t)idx * 4];
    fp[0] = (ep / s) / (SEP + EPS_BAL);
    fp[1] = (et / s) / (SET + EPS_BAL);
    fp[2] = (ec / s) / (ec  + EPS_BAL);
    fp[3] = 0.f;
}

// --------------------------------------- streaming A materialization
__global__ __launch_bounds__(256)
void mat_kernel(const float* __restrict__ A_raw, const float* __restrict__ fac,
                float* __restrict__ A) {
    const size_t row = blockIdx.x;
    const float* src = A_raw + row * cN;
    float* dst = A + row * cN;
    const float4 f = *(const float4*)&fac[row * 4];
    const int t = threadIdx.x;
    #pragma unroll
    for (int i = 0; i < 8; i++) {
        int idx = t + i * 256;
        dst[idx] = __expf(src[idx]) * f.x;
    }
    if (t < 17) {
        int idx = cNP + t;
        float ff = (t < 16) ? f.y : f.z;
        dst[idx] = __expf(src[idx]) * ff;
    }
}

// --------------------- tf32 AV GEMM, cp.async double-buffered (reads A)
__global__ __launch_bounds__(256)
void avg_kernel(const float* __restrict__ A, const float* __restrict__ qkv,
                float* __restrict__ OH) {
    const int t = threadIdx.x, lane = t & 31, wid = t >> 5;
    const int wrow = wid >> 1, wcol = wid & 1;
    const int bh = blockIdx.y, b = bh >> 3, h = bh & 7;
    const int n0 = blockIdx.x * 128;

    float*    Ab = dynsm;                              // [2][128][68] fp32
    uint32_t* Vb = (uint32_t*)(dynsm + 2 * 128 * 68);  // [2][64][68] tf32 V^T
    const uint32_t sAb = (uint32_t)__cvta_generic_to_shared(Ab);

    const float* Arow = A + (size_t)bh * cN * cN;
    const float* vb = qkv + (size_t)b * cN * cE3 + 2 * cE + h * 64;

    const int vd = t & 63, vmg = t >> 6;
    float acc[2][4][4] = {};

    {
        const int m0 = 0;
        #pragma unroll
        for (int i = 0; i < 32; i++) {
            int idx = t + i * 256;
            int row = idx >> 6, col = idx & 63;
            int n = n0 + row, m = m0 + col;
            bool ok = (n < cN) && (m < cN);
            const float* src = &Arow[(size_t)(ok ? n : 0) * cN + (ok ? m : 0)];
            cp_async4(sAb + (uint32_t)((row*68 + col) * 4), src, ok);
        }
        uint32_t* Vd = Vb + vd * 68;
        #pragma unroll
        for (int j = 0; j < 4; j++) {
            int ml = vmg * 16 + j * 4;
            float4 v;
            v.x = (m0+ml+0 < cN) ? vb[(size_t)(m0+ml+0)*cE3 + vd] : 0.f;
            v.y = (m0+ml+1 < cN) ? vb[(size_t)(m0+ml+1)*cE3 + vd] : 0.f;
            v.z = (m0+ml+2 < cN) ? vb[(size_t)(m0+ml+2)*cE3 + vd] : 0.f;
            v.w = (m0+ml+3 < cN) ? vb[(size_t)(m0+ml+3)*cE3 + vd] : 0.f;
            *(uint4*)&Vd[ml] = make_uint4(f2tf32(v.x), f2tf32(v.y),
                                          f2tf32(v.z), f2tf32(v.w));
        }
    }
    cp_commit();

    for (int c = 0; c < NCH; c++) {
        if (c + 1 < NCH) {
            const int m0 = (c + 1) * 64;
            const uint32_t bufo = (uint32_t)(((c + 1) & 1) * 128 * 68 * 4);
            #pragma unroll
            for (int i = 0; i < 32; i++) {
                int idx = t + i * 256;
                int row = idx >> 6, col = idx & 63;
                int n = n0 + row, m = m0 + col;
                bool ok = (n < cN) && (m < cN);
                const float* src = &Arow[(size_t)(ok ? n : 0) * cN + (ok ? m : 0)];
                cp_async4(sAb + bufo + (uint32_t)((row*68 + col) * 4), src, ok);
            }
            uint32_t* Vd = Vb + ((c + 1) & 1) * 64 * 68 + vd * 68;
            #pragma unroll
            for (int j = 0; j < 4; j++) {
                int ml = vmg * 16 + j * 4;
                float4 v;
                v.x = (m0+ml+0 < cN) ? vb[(size_t)(m0+ml+0)*cE3 + vd] : 0.f;
                v.y = (m0+ml+1 < cN) ? vb[(size_t)(m0+ml+1)*cE3 + vd] : 0.f;
                v.z = (m0+ml+2 < cN) ? vb[(size_t)(m0+ml+2)*cE3 + vd] : 0.f;
                v.w = (m0+ml+3 < cN) ? vb[(size_t)(m0+ml+3)*cE3 + vd] : 0.f;
                *(uint4*)&Vd[ml] = make_uint4(f2tf32(v.x), f2tf32(v.y),
                                              f2tf32(v.z), f2tf32(v.w));
            }
        }
        cp_commit();
        cp_wait1();
        __syncthreads();

        const float*    Ac = Ab + (c & 1) * 128 * 68;
        const uint32_t* Vc = Vb + (c & 1) * 64 * 68;
        #pragma unroll
        for (int kk = 0; kk < 8; kk++) {
            const int k0 = kk * 8;
            uint32_t a[2][4], bq[4][2];
            #pragma unroll
            for (int mt = 0; mt < 2; mt++) {
                int r = wrow*32 + mt*16 + (lane >> 2);
                a[mt][0] = f2tf32(Ac[r*68     + k0     + (lane & 3)]);
                a[mt][1] = f2tf32(Ac[(r+8)*68 + k0     + (lane & 3)]);
                a[mt][2] = f2tf32(Ac[r*68     + k0 + 4 + (lane & 3)]);
                a[mt][3] = f2tf32(Ac[(r+8)*68 + k0 + 4 + (lane & 3)]);
            }
            #pragma unroll
            for (int nt = 0; nt < 4; nt++) {
                int dd = wcol*32 + nt*8 + (lane >> 2);
                bq[nt][0] = Vc[dd*68 + k0     + (lane & 3)];
                bq[nt][1] = Vc[dd*68 + k0 + 4 + (lane & 3)];
            }
            #pragma unroll
            for (int mt = 0; mt < 2; mt++)
                #pragma unroll
                for (int nt = 0; nt < 4; nt++)
                    mma_tf32(acc[mt][nt], a[mt][0], a[mt][1], a[mt][2], a[mt][3],
                             bq[nt][0], bq[nt][1]);
        }
        __syncthreads();
    }

    #pragma unroll
    for (int mt = 0; mt < 2; mt++) {
        #pragma unroll
        for (int nt = 0; nt < 4; nt++) {
            int n = n0 + wrow*32 + mt*16 + (lane >> 2);
            int d = wcol*32 + nt*8 + (lane & 3)*2;
            if (n < cN)
                *(float2*)&OH[((size_t)b * cN + n) * cE + h*64 + d] =
                    make_float2(acc[mt][nt][0], acc[mt][nt][1]);
            if (n + 8 < cN)
                *(float2*)&OH[((size_t)b * cN + n + 8) * cE + h*64 + d] =
                    make_float2(acc[mt][nt][2], acc[mt][nt][3]);
        }
    }
}

// ---------------------------------------------------------------------------
extern "C" void kernel_launch(void* const* d_in, const int* in_sizes, int n_in,
                              void* d_out, int out_size) {
    const float* x     = (const float*)d_in[0];
    const float* w_qkv = (const float*)d_in[1];
    const float* b_qkv = (const float*)d_in[2];
    const float* w_out = (const float*)d_in[3];
    const float* b_out = (const float*)d_in[4];

    float* out   = (float*)d_out;
    float* A     = out + (size_t)cB * cN * cE;
    float* A_raw = A   + (size_t)NBH * cN * cN;

    float *qkv = nullptr, *oh = nullptr, *facp = nullptr, *partp = nullptr;
    cudaGetSymbolAddress((void**)&qkv,   g_qkv);
    cudaGetSymbolAddress((void**)&oh,    g_oh);
    cudaGetSymbolAddress((void**)&facp,  g_fac);
    cudaGetSymbolAddress((void**)&partp, g_part);

    const int M = cB * cN;
    const int QK_SMEM  = 2 * 128 * 68 * 4;                 // 69632 B
    const int AVG_SMEM = (2*128*68 + 2*64*68) * 4;         // 104448 B
    cudaFuncSetAttribute(qk_kernel,  cudaFuncAttributeMaxDynamicSharedMemorySize, QK_SMEM);
    cudaFuncSetAttribute(avg_kernel, cudaFuncAttributeMaxDynamicSharedMemorySize, AVG_SMEM);

    gemm_tf32_bias<<<dim3(cE3/128, (M+127)/128), 256>>>(x, w_qkv, b_qkv, qkv, M, cE3, cE);
    qk_kernel<<<dim3(17, 17, NBH), 256, QK_SMEM>>>(qkv, A_raw, partp);
    finalize_kernel<<<(NBH*cN + 255)/256, 256>>>(partp, facp);
    mat_kernel<<<NBH * cN, 256>>>(A_raw, facp, A);
    avg_kernel<<<dim3(17, NBH), 256, AVG_SMEM>>>(A, qkv, oh);
    gemm_tf32_bias<<<dim3(cE/128, (M+127)/128), 256>>>(oh, w_out, b_out, out, M, cE, cE);
}